// round 8
// baseline (speedup 1.0000x reference)
#include <cuda_runtime.h>
#include <cuda_bf16.h>
#include <math.h>

// ---------------- scratch (device globals: allocation-free) ----------------
static __device__ float g_y[52428800];        // conv1 out: (512,256,20,20)  209.7 MB
static __device__ float g_u[4718592];         // u: (512,1152,8)             18.9 MB
static __device__ float g_priors[94371840];   // priors: (512,10,1152,16)    377.5 MB
static __device__ float g_logits[5120];       // (512,10) pre-softmax

// ---------------- conv1: x(512,1,28,28) * w(256,1,9,9) -> y(512,256,20,20) ----------------
// One block per batch image; one thread per output channel (weights in registers).
__global__ void __launch_bounds__(256) conv1_kernel(const float* __restrict__ x,
                                                    const float* __restrict__ w,
                                                    const float* __restrict__ cb) {
    __shared__ float s_img[784];
    int b = blockIdx.x;
    int co = threadIdx.x;
    for (int i = threadIdx.x; i < 784; i += 256) s_img[i] = x[b * 784 + i];
    float wreg[81];
#pragma unroll
    for (int j = 0; j < 81; j++) wreg[j] = w[co * 81 + j];
    float bs = cb[co];
    __syncthreads();
    float* outp = g_y + ((size_t)b * 256 + co) * 400;
    for (int oh = 0; oh < 20; oh++) {
        for (int owg = 0; owg < 20; owg += 4) {
            float a0 = bs, a1 = bs, a2 = bs, a3 = bs;
#pragma unroll
            for (int kh = 0; kh < 9; kh++) {
                const float* ip = &s_img[(oh + kh) * 28 + owg];
#pragma unroll
                for (int kw = 0; kw < 9; kw++) {
                    float wv = wreg[kh * 9 + kw];
                    a0 = fmaf(ip[kw + 0], wv, a0);
                    a1 = fmaf(ip[kw + 1], wv, a1);
                    a2 = fmaf(ip[kw + 2], wv, a2);
                    a3 = fmaf(ip[kw + 3], wv, a3);
                }
            }
            *reinterpret_cast<float4*>(outp + oh * 20 + owg) = make_float4(a0, a1, a2, a3);
        }
    }
}

// ---------------- conv2 as implicit GEMM ----------------
// C[co(256), n(18432)] = W[co, k(20736)] * Patch[k, n]
// k = ci*81 + kh*9 + kw ; n = b*36 + oh*6 + ow ; Patch[k][n] = y[b,ci,2oh+kh,2ow+kw]
// Tiles: BM=64(co) x BN=128(n) x BK=16, 256 threads, 4x8 per-thread tile.
// Epilogue writes directly into u layout: u[b, r=(co%32)*36+pos, d=co/32] = p + bias
__global__ void __launch_bounds__(256) conv2_kernel(const float* __restrict__ w,
                                                    const float* __restrict__ pb) {
    __shared__ float As[16][64];
    __shared__ float Bs[16][128];
    __shared__ int s_nbase[128];
    int tid = threadIdx.x;
    int n0 = blockIdx.x * 128;
    int m0 = blockIdx.y * 64;
    if (tid < 128) {
        int n = n0 + tid;
        int b = n / 36, pos = n - b * 36;
        int oh = pos / 6, ow = pos - oh * 6;
        s_nbase[tid] = b * 102400 + oh * 40 + ow * 2;
    }
    __syncthreads();
    int mg = tid >> 4, ng = tid & 15;
    float acc[4][8];
#pragma unroll
    for (int i = 0; i < 4; i++)
#pragma unroll
        for (int j = 0; j < 8; j++) acc[i][j] = 0.f;

    int a_m = tid >> 2;              // 0..63
    int a_k = (tid & 3) << 2;        // 0,4,8,12
    int b_k = tid >> 4;              // 0..15
    int b_n = (tid & 15) << 3;       // 0..120
    const float* wrow = w + (size_t)(m0 + a_m) * 20736 + a_k;

    for (int k0 = 0; k0 < 20736; k0 += 16) {
        // stage global loads in registers (overlap with previous compute)
        float4 av = *reinterpret_cast<const float4*>(wrow + k0);
        int kk = k0 + b_k;
        int ci = kk / 81;
        int rr = kk - ci * 81;
        int kh = rr / 9;
        int kw = rr - kh * 9;
        int koff = ci * 400 + kh * 20 + kw;
        float bv[8];
#pragma unroll
        for (int j = 0; j < 8; j++) bv[j] = g_y[s_nbase[b_n + j] + koff];

        __syncthreads();
        As[a_k + 0][a_m] = av.x;
        As[a_k + 1][a_m] = av.y;
        As[a_k + 2][a_m] = av.z;
        As[a_k + 3][a_m] = av.w;
#pragma unroll
        for (int j = 0; j < 8; j++) Bs[b_k][b_n + j] = bv[j];
        __syncthreads();

#pragma unroll
        for (int k = 0; k < 16; k++) {
            float4 a4 = *reinterpret_cast<const float4*>(&As[k][mg << 2]);
            float4 b0 = *reinterpret_cast<const float4*>(&Bs[k][ng << 3]);
            float4 b1 = *reinterpret_cast<const float4*>(&Bs[k][(ng << 3) + 4]);
            float ar[4] = {a4.x, a4.y, a4.z, a4.w};
            float br[8] = {b0.x, b0.y, b0.z, b0.w, b1.x, b1.y, b1.z, b1.w};
#pragma unroll
            for (int i = 0; i < 4; i++)
#pragma unroll
                for (int j = 0; j < 8; j++) acc[i][j] = fmaf(ar[i], br[j], acc[i][j]);
        }
    }

#pragma unroll
    for (int i = 0; i < 4; i++) {
        int co = m0 + (mg << 2) + i;
        float bias = pb[co];
        int cm = co & 31, d = co >> 5;
#pragma unroll
        for (int j = 0; j < 8; j++) {
            int n = n0 + (ng << 3) + j;
            int b = n / 36, pos = n - b * 36;
            int r = cm * 36 + pos;
            g_u[((size_t)b * 1152 + r) * 8 + d] = acc[i][j] + bias;
        }
    }
}

// ---------------- squash u in place (per 8-dim capsule vector) ----------------
__global__ void squash_kernel() {
    int idx = blockIdx.x * 256 + threadIdx.x;
    if (idx >= 512 * 1152) return;
    float4 v0 = *reinterpret_cast<float4*>(&g_u[(size_t)idx * 8]);
    float4 v1 = *reinterpret_cast<float4*>(&g_u[(size_t)idx * 8 + 4]);
    float sn = v0.x * v0.x + v0.y * v0.y + v0.z * v0.z + v0.w * v0.w +
               v1.x * v1.x + v1.y * v1.y + v1.z * v1.z + v1.w * v1.w;
    float sc = sqrtf(sn) / (1.f + sn);
    v0.x *= sc; v0.y *= sc; v0.z *= sc; v0.w *= sc;
    v1.x *= sc; v1.y *= sc; v1.z *= sc; v1.w *= sc;
    *reinterpret_cast<float4*>(&g_u[(size_t)idx * 8]) = v0;
    *reinterpret_cast<float4*>(&g_u[(size_t)idx * 8 + 4]) = v1;
}

// ---------------- priors[b,c,r,o] = sum_i u[b,r,i] * route_w[c,r,i,o] ----------------
// Block = (r-chunk of 16, c); route_w slice cached in smem, loop over all b.
__global__ void __launch_bounds__(256) priors_kernel(const float* __restrict__ rw) {
    __shared__ float s_w[2048];   // 16 r x 8 i x 16 o
    __shared__ float s_u[128];    // 16 r x 8 i
    int tid = threadIdx.x;
    int r0 = blockIdx.x * 16;
    int c = blockIdx.y;
    const float* wsrc = rw + (size_t)c * 147456 + (size_t)r0 * 128;
    for (int i = tid; i < 2048; i += 256) s_w[i] = wsrc[i];
    int rl = tid >> 4, o = tid & 15;
    float* pdst = g_priors + (size_t)c * 18432 + (size_t)r0 * 16 + tid;
    for (int b = 0; b < 512; b++) {
        if (tid < 128) s_u[tid] = g_u[(size_t)b * 9216 + r0 * 8 + tid];
        __syncthreads();
        float acc = 0.f;
#pragma unroll
        for (int i = 0; i < 8; i++)
            acc = fmaf(s_u[rl * 8 + i], s_w[rl * 128 + i * 16 + o], acc);
        pdst[(size_t)b * 184320] = acc;
        __syncthreads();
    }
}

// ---------------- routing: one block per (b,c); 3 iterations entirely in smem ----------------
__device__ __forceinline__ float blk_reduce_max(float v, float* red) {
#pragma unroll
    for (int s = 16; s; s >>= 1) v = fmaxf(v, __shfl_xor_sync(0xffffffffu, v, s));
    if ((threadIdx.x & 31) == 0) red[threadIdx.x >> 5] = v;
    __syncthreads();
    float r = red[0];
#pragma unroll
    for (int i = 1; i < 8; i++) r = fmaxf(r, red[i]);
    __syncthreads();
    return r;
}

__device__ __forceinline__ float blk_reduce_sum(float v, float* red) {
#pragma unroll
    for (int s = 16; s; s >>= 1) v += __shfl_xor_sync(0xffffffffu, v, s);
    if ((threadIdx.x & 31) == 0) red[threadIdx.x >> 5] = v;
    __syncthreads();
    float r = red[0];
#pragma unroll
    for (int i = 1; i < 8; i++) r += red[i];
    __syncthreads();
    return r;
}

__global__ void __launch_bounds__(256) routing_kernel() {
    extern __shared__ float sm[];
    float* P     = sm;          // [1152][17] padded (conflict-free) : 19584
    float* blog  = sm + 19584;  // 1152
    float* probs = sm + 20736;  // 1152
    float* sred  = sm + 21888;  // 256
    float* s_s   = sm + 22144;  // 16
    float* s_v   = sm + 22160;  // 16
    float* red   = sm + 22176;  // 8

    int tid = threadIdx.x;
    int b = blockIdx.x, c = blockIdx.y;
    const float* gp = g_priors + ((size_t)b * 10 + c) * 18432;
    for (int idx = tid; idx < 18432; idx += 256) {
        int r = idx >> 4, o = idx & 15;
        P[r * 17 + o] = gp[idx];
    }
    for (int r = tid; r < 1152; r += 256) blog[r] = 0.f;
    __syncthreads();

    int o = tid & 15, rg = tid >> 4;
    for (int it = 0; it < 3; it++) {
        // softmax(blog) over r -> probs (unnormalized; inv applied to s)
        float mx = -1e30f;
        for (int r = tid; r < 1152; r += 256) mx = fmaxf(mx, blog[r]);
        mx = blk_reduce_max(mx, red);
        float se = 0.f;
        for (int r = tid; r < 1152; r += 256) {
            float e = expf(blog[r] - mx);
            probs[r] = e;
            se += e;
        }
        se = blk_reduce_sum(se, red);
        float inv = 1.f / se;

        // s[o] = sum_r probs[r] * P[r][o]
        float acc = 0.f;
        for (int r = rg; r < 1152; r += 16) acc = fmaf(probs[r], P[r * 17 + o], acc);
        sred[tid] = acc;
        __syncthreads();
        if (tid < 16) {
            float s = 0.f;
#pragma unroll
            for (int g = 0; g < 16; g++) s += sred[g * 16 + tid];
            s_s[tid] = s * inv;
        }
        __syncthreads();
        // v = squash(s); logit = |v| = sn/(1+sn)
        if (tid < 16) {
            float sn = 0.f;
#pragma unroll
            for (int oo = 0; oo < 16; oo++) sn += s_s[oo] * s_s[oo];
            float sc = sqrtf(sn) / (1.f + sn);
            s_v[tid] = s_s[tid] * sc;
            if (tid == 0 && it == 2) g_logits[b * 10 + c] = sn / (1.f + sn);
        }
        __syncthreads();
        // blog[r] += sum_o P[r][o] * v[o]  (dead on final iteration)
        if (it < 2) {
            for (int r = tid; r < 1152; r += 256) {
                float a = 0.f;
#pragma unroll
                for (int oo = 0; oo < 16; oo++) a = fmaf(P[r * 17 + oo], s_v[oo], a);
                blog[r] += a;
            }
            __syncthreads();
        }
    }
}

// ---------------- final softmax over 10 classes ----------------
__global__ void final_kernel(float* __restrict__ out) {
    int b = blockIdx.x * blockDim.x + threadIdx.x;
    if (b >= 512) return;
    float l[10];
    float mx = -1e30f;
#pragma unroll
    for (int i = 0; i < 10; i++) { l[i] = g_logits[b * 10 + i]; mx = fmaxf(mx, l[i]); }
    float se = 0.f;
#pragma unroll
    for (int i = 0; i < 10; i++) { l[i] = expf(l[i] - mx); se += l[i]; }
    float inv = 1.f / se;
#pragma unroll
    for (int i = 0; i < 10; i++) out[b * 10 + i] = l[i] * inv;
}

// ---------------- launch ----------------
extern "C" void kernel_launch(void* const* d_in, const int* in_sizes, int n_in,
                              void* d_out, int out_size) {
    const float* x       = (const float*)d_in[0];
    const float* conv_w  = (const float*)d_in[1];
    const float* conv_b  = (const float*)d_in[2];
    const float* prim_w  = (const float*)d_in[3];
    const float* prim_b  = (const float*)d_in[4];
    const float* route_w = (const float*)d_in[5];
    float* out = (float*)d_out;

    conv1_kernel<<<512, 256>>>(x, conv_w, conv_b);
    conv2_kernel<<<dim3(144, 4), 256>>>(prim_w, prim_b);
    squash_kernel<<<2304, 256>>>();
    priors_kernel<<<dim3(72, 10), 256>>>(route_w);
    cudaFuncSetAttribute(routing_kernel, cudaFuncAttributeMaxDynamicSharedMemorySize, 90112);
    routing_kernel<<<dim3(512, 10), 256, 22184 * 4>>>();
    final_kernel<<<2, 256>>>(out);
}